// round 14
// baseline (speedup 1.0000x reference)
#include <cuda_runtime.h>
#include <cuda_fp16.h>

#define NN 50000
#define NE 800000
#define NF 128
#define NH 64
#define NL 3
#define NG 512
#define NC 10
#define SCAN_B 196   // ceil(50000/256)
#define BN_EPS 1e-5f
#define NTILE 3125   // 50000 / 16
#define EGRID 391    // enc: 8 warps/block, 1 tile per warp
#define LWARPS 4     // layer: warps per block
#define LGRID 782    // ceil(3125/4) -> 1 tile per warp, 4-warp blocks

// Scratch (no allocations allowed). All zero-initialized at module load;
// final_kernel re-zeroes the mutable ones at the END of every launch.
__device__ float g_h[NN * NH];            // node features fp32 (post BN+ReLU)
__device__ unsigned g_hh[NN * NH / 2];    // fp16x2 mirror (neighbor reads)
__device__ float g_t[NN * NH];            // raw MLP output (pre-BN)
__device__ float g_stats[NL][2 * NH];
__device__ float g_pool[NG * NH];
__device__ float g_cnt[NG];
// CSR scratch
__device__ int g_deg[NN];
__device__ int g_off[NN];
__device__ int g_rank[NE];
__device__ int g_csr[NE];
__device__ int g_ecnt;

__device__ __forceinline__ unsigned smem_u32(const void* p) {
    unsigned a;
    asm("{ .reg .u64 t; cvta.to.shared.u64 t, %1; cvt.u32.u64 %0, t; }"
        : "=r"(a) : "l"(p));
    return a;
}

// ---------------------------------------------------------------------------
__global__ void hist_kernel(const int* __restrict__ ei) {
    int t = blockIdx.x * blockDim.x + threadIdx.x;
    if (t >= NE / 4) return;
    int4 d = ((const int4*)(ei + NE))[t];
    int4 r;
    r.x = atomicAdd(&g_deg[d.x], 1);
    r.y = atomicAdd(&g_deg[d.y], 1);
    r.z = atomicAdd(&g_deg[d.z], 1);
    r.w = atomicAdd(&g_deg[d.w], 1);
    ((int4*)g_rank)[t] = r;
}

__global__ void scan_fused_kernel() {
    __shared__ int s[256];
    __shared__ int sbase;
    int tid = threadIdx.x, i = blockIdx.x * 256 + tid;
    int v = (i < NN) ? g_deg[i] : 0;
    s[tid] = v;
    __syncthreads();
#pragma unroll
    for (int d = 1; d < 256; d <<= 1) {
        int t = (tid >= d) ? s[tid - d] : 0;
        __syncthreads();
        s[tid] += t;
        __syncthreads();
    }
    if (tid == 255) sbase = atomicAdd(&g_ecnt, s[255]);
    __syncthreads();
    if (i < NN) g_off[i] = sbase + s[tid] - v;
}

__global__ void fill_kernel(const int* __restrict__ ei) {
    int t = blockIdx.x * blockDim.x + threadIdx.x;
    if (t >= NE / 4) return;
    int4 s = ((const int4*)ei)[t];
    int4 d = ((const int4*)(ei + NE))[t];
    int4 r = ((const int4*)g_rank)[t];
    g_csr[__ldg(&g_off[d.x]) + r.x] = s.x;
    g_csr[__ldg(&g_off[d.y]) + r.y] = s.y;
    g_csr[__ldg(&g_off[d.z]) + r.z] = s.z;
    g_csr[__ldg(&g_off[d.w]) + r.w] = s.w;
}

// ---------------------------------------------------------------------------
// Tensor-core encoder (unchanged)
// ---------------------------------------------------------------------------
__global__ void enc_kernel(const float* __restrict__ x,
                           const float* __restrict__ w,
                           const float* __restrict__ b) {
    __shared__ __align__(16) __half sWe[2][NH * 72];
    __shared__ __align__(16) __half sA[8][16 * 72];
    __shared__ float sbb[NH];
    int tid = threadIdx.x, wid = tid >> 5, lane = tid & 31;
    int half_ = lane >> 4, lane16 = lane & 15;
    __half* hh = (__half*)g_hh;

    for (int i = tid; i < NF * NH; i += 256) {
        int k = i >> 6, n = i & 63;
        sWe[k >> 6][n * 72 + (k & 63)] = __float2half_rn(w[i]);
    }
    if (tid < NH) sbb[tid] = __ldg(b + tid);
    __syncthreads();

    __half* myA = sA[wid];
    unsigned aBase = smem_u32(myA);
    unsigned wBase0 = smem_u32(sWe[0]);
    unsigned wBase1 = smem_u32(sWe[1]);

    int aRow = lane & 15;
    int aColOfs = (lane >= 16) ? 8 : 0;
    int bRowOfs = lane & 7;
    int bColOfs = (lane & 8) ? 8 : 0;
    int col0 = (lane & 3) * 2;
    int r = lane >> 2;

    for (int wt = blockIdx.x * 8 + wid; wt < NTILE; wt += gridDim.x * 8) {
        int n0 = wt * 16;
        float c[8][4];
#pragma unroll
        for (int nt = 0; nt < 8; nt++)
#pragma unroll
            for (int i = 0; i < 4; i++) c[nt][i] = 0.0f;

#pragma unroll
        for (int h = 0; h < 2; h++) {
#pragma unroll
            for (int p = 0; p < 8; p++) {
                int row = p * 2 + half_;
                float4 v = *(const float4*)(x + (size_t)(n0 + row) * NF + h * 64 + lane16 * 4);
                __half2 lo = __floats2half2_rn(v.x, v.y);
                __half2 hi = __floats2half2_rn(v.z, v.w);
                uint2 u;
                u.x = *(unsigned*)&lo;
                u.y = *(unsigned*)&hi;
                *(uint2*)(myA + row * 72 + lane16 * 4) = u;
            }
            __syncwarp();

            unsigned A[4][4];
#pragma unroll
            for (int kb = 0; kb < 4; kb++) {
                unsigned addr = aBase + (aRow * 72 + kb * 16 + aColOfs) * 2;
                asm volatile("ldmatrix.sync.aligned.m8n8.x4.shared.b16 {%0,%1,%2,%3}, [%4];"
                             : "=r"(A[kb][0]), "=r"(A[kb][1]), "=r"(A[kb][2]), "=r"(A[kb][3])
                             : "r"(addr));
            }
            unsigned wBase = h ? wBase1 : wBase0;
#pragma unroll
            for (int nt = 0; nt < 8; nt++) {
#pragma unroll
                for (int kb = 0; kb < 4; kb++) {
                    unsigned b0, b1r;
                    unsigned addr = wBase + ((nt * 8 + bRowOfs) * 72 + kb * 16 + bColOfs) * 2;
                    asm volatile("ldmatrix.sync.aligned.m8n8.x2.shared.b16 {%0,%1}, [%2];"
                                 : "=r"(b0), "=r"(b1r) : "r"(addr));
                    asm volatile("mma.sync.aligned.m16n8k16.row.col.f32.f16.f16.f32 "
                                 "{%0,%1,%2,%3}, {%4,%5,%6,%7}, {%8,%9}, {%0,%1,%2,%3};"
                                 : "+f"(c[nt][0]), "+f"(c[nt][1]), "+f"(c[nt][2]), "+f"(c[nt][3])
                                 : "r"(A[kb][0]), "r"(A[kb][1]), "r"(A[kb][2]), "r"(A[kb][3]),
                                   "r"(b0), "r"(b1r));
                }
            }
            __syncwarp();
        }

#pragma unroll
        for (int nt = 0; nt < 8; nt++) {
            float bb0 = sbb[nt * 8 + col0], bb1 = sbb[nt * 8 + col0 + 1];
            float c0 = c[nt][0] + bb0, c1 = c[nt][1] + bb1;
            float c2 = c[nt][2] + bb0, c3 = c[nt][3] + bb1;
            size_t i0 = (size_t)(n0 + r) * NH + nt * 8 + col0;
            size_t i1 = (size_t)(n0 + r + 8) * NH + nt * 8 + col0;
            *(float2*)&g_h[i0] = make_float2(c0, c1);
            *(float2*)&g_h[i1] = make_float2(c2, c3);
            *(__half2*)&hh[i0] = __floats2half2_rn(c0, c1);
            *(__half2*)&hh[i1] = __floats2half2_rn(c2, c3);
        }
    }
}

// ---------------------------------------------------------------------------
// Fused layer. Gather restructured: QUARTER-warp (8 lanes) per node,
// uint4 (16B) neighbor loads -> 4 concurrent chains/warp, LDG.128.
// ---------------------------------------------------------------------------
__global__ void layer_kernel(const float* __restrict__ epsl, int l,
                             const float* __restrict__ w1, const float* __restrict__ b1,
                             const float* __restrict__ w2, const float* __restrict__ b2) {
    __shared__ __align__(16) __half sW1[NH * 72];
    __shared__ __align__(16) __half sW2[NH * 72];
    __shared__ __align__(16) __half sA[LWARPS][16 * 72];
    __shared__ float sb1[NH], sb2[NH];
    __shared__ float ssum[NH], ssq[NH];

    int tid = threadIdx.x, wid = tid >> 5, lane = tid & 31;
    int q8 = lane >> 3, lane8 = lane & 7;
    unsigned qmask = 0xFFu << (q8 * 8);

    for (int i = tid; i < NH * NH; i += LWARPS * 32) {
        int k = i >> 6, n = i & 63;
        sW1[n * 72 + k] = __float2half_rn(w1[i]);
        sW2[n * 72 + k] = __float2half_rn(w2[i]);
    }
    if (tid < NH) {
        sb1[tid] = __ldg(b1 + tid);
        sb2[tid] = __ldg(b2 + tid);
        ssum[tid] = 0.0f; ssq[tid] = 0.0f;
    }
    __syncthreads();

    float se = 1.0f + __ldg(epsl);
    __half* myA = sA[wid];
    unsigned aBase = smem_u32(myA);
    unsigned w1Base = smem_u32(sW1);
    unsigned w2Base = smem_u32(sW2);

    int aRow = lane & 15;
    int aColOfs = (lane >= 16) ? 8 : 0;
    int bRowOfs = lane & 7;
    int bColOfs = (lane & 8) ? 8 : 0;
    int col0 = (lane & 3) * 2;
    int r = lane >> 2;

    float st_s[16], st_q[16];
#pragma unroll
    for (int i = 0; i < 16; i++) { st_s[i] = 0.0f; st_q[i] = 0.0f; }

    for (int wt = blockIdx.x * LWARPS + wid; wt < NTILE; wt += gridDim.x * LWARPS) {
        int n0 = wt * 16;
        // ---- gather: 4 quarter-warps x 4 rounds = 16 nodes ----
#pragma unroll
        for (int pp = 0; pp < 4; pp++) {
            int node = n0 + pp * 4 + q8;
            const float* selfp = g_h + (size_t)node * NH + lane8 * 8;
            float4 a0 = *(const float4*)selfp;
            float4 a1 = *(const float4*)(selfp + 4);
            a0.x *= se; a0.y *= se; a0.z *= se; a0.w *= se;
            a1.x *= se; a1.y *= se; a1.z *= se; a1.w *= se;

            int begin = __ldg(&g_off[node]);
            int end   = begin + __ldg(&g_deg[node]);
            for (int base = begin; base < end; base += 8) {
                int cnt = min(8, end - base);
                int sidx = (lane8 < cnt) ? __ldg(&g_csr[base + lane8]) : 0;
                int j = 0;
                for (; j + 4 <= cnt; j += 4) {
                    int s0 = __shfl_sync(qmask, sidx, j + 0, 8);
                    int s1 = __shfl_sync(qmask, sidx, j + 1, 8);
                    int s2 = __shfl_sync(qmask, sidx, j + 2, 8);
                    int s3 = __shfl_sync(qmask, sidx, j + 3, 8);
                    uint4 v0 = *(const uint4*)(g_hh + (size_t)s0 * 32 + lane8 * 4);
                    uint4 v1 = *(const uint4*)(g_hh + (size_t)s1 * 32 + lane8 * 4);
                    uint4 v2 = *(const uint4*)(g_hh + (size_t)s2 * 32 + lane8 * 4);
                    uint4 v3 = *(const uint4*)(g_hh + (size_t)s3 * 32 + lane8 * 4);
                    float2 f;
                    f = __half22float2(*(__half2*)&v0.x); a0.x += f.x; a0.y += f.y;
                    f = __half22float2(*(__half2*)&v0.y); a0.z += f.x; a0.w += f.y;
                    f = __half22float2(*(__half2*)&v0.z); a1.x += f.x; a1.y += f.y;
                    f = __half22float2(*(__half2*)&v0.w); a1.z += f.x; a1.w += f.y;
                    f = __half22float2(*(__half2*)&v1.x); a0.x += f.x; a0.y += f.y;
                    f = __half22float2(*(__half2*)&v1.y); a0.z += f.x; a0.w += f.y;
                    f = __half22float2(*(__half2*)&v1.z); a1.x += f.x; a1.y += f.y;
                    f = __half22float2(*(__half2*)&v1.w); a1.z += f.x; a1.w += f.y;
                    f = __half22float2(*(__half2*)&v2.x); a0.x += f.x; a0.y += f.y;
                    f = __half22float2(*(__half2*)&v2.y); a0.z += f.x; a0.w += f.y;
                    f = __half22float2(*(__half2*)&v2.z); a1.x += f.x; a1.y += f.y;
                    f = __half22float2(*(__half2*)&v2.w); a1.z += f.x; a1.w += f.y;
                    f = __half22float2(*(__half2*)&v3.x); a0.x += f.x; a0.y += f.y;
                    f = __half22float2(*(__half2*)&v3.y); a0.z += f.x; a0.w += f.y;
                    f = __half22float2(*(__half2*)&v3.z); a1.x += f.x; a1.y += f.y;
                    f = __half22float2(*(__half2*)&v3.w); a1.z += f.x; a1.w += f.y;
                }
                for (; j < cnt; j++) {
                    int s0 = __shfl_sync(qmask, sidx, j, 8);
                    uint4 v0 = *(const uint4*)(g_hh + (size_t)s0 * 32 + lane8 * 4);
                    float2 f;
                    f = __half22float2(*(__half2*)&v0.x); a0.x += f.x; a0.y += f.y;
                    f = __half22float2(*(__half2*)&v0.y); a0.z += f.x; a0.w += f.y;
                    f = __half22float2(*(__half2*)&v0.z); a1.x += f.x; a1.y += f.y;
                    f = __half22float2(*(__half2*)&v0.w); a1.z += f.x; a1.w += f.y;
                }
            }
            __half2 h0 = __floats2half2_rn(a0.x, a0.y);
            __half2 h1 = __floats2half2_rn(a0.z, a0.w);
            __half2 h2 = __floats2half2_rn(a1.x, a1.y);
            __half2 h3 = __floats2half2_rn(a1.z, a1.w);
            uint4 u;
            u.x = *(unsigned*)&h0;
            u.y = *(unsigned*)&h1;
            u.z = *(unsigned*)&h2;
            u.w = *(unsigned*)&h3;
            *(uint4*)(myA + (pp * 4 + q8) * 72 + lane8 * 8) = u;
        }
        __syncwarp();

        unsigned A1[4][4];
#pragma unroll
        for (int kb = 0; kb < 4; kb++) {
            unsigned addr = aBase + (aRow * 72 + kb * 16 + aColOfs) * 2;
            asm volatile("ldmatrix.sync.aligned.m8n8.x4.shared.b16 {%0,%1,%2,%3}, [%4];"
                         : "=r"(A1[kb][0]), "=r"(A1[kb][1]), "=r"(A1[kb][2]), "=r"(A1[kb][3])
                         : "r"(addr));
        }
        __syncwarp();

#pragma unroll
        for (int nt = 0; nt < 8; nt++) {
            float c0 = 0.f, c1 = 0.f, c2 = 0.f, c3 = 0.f;
#pragma unroll
            for (int kb = 0; kb < 4; kb++) {
                unsigned b0, b1r;
                unsigned addr = w1Base + ((nt * 8 + bRowOfs) * 72 + kb * 16 + bColOfs) * 2;
                asm volatile("ldmatrix.sync.aligned.m8n8.x2.shared.b16 {%0,%1}, [%2];"
                             : "=r"(b0), "=r"(b1r) : "r"(addr));
                asm volatile("mma.sync.aligned.m16n8k16.row.col.f32.f16.f16.f32 "
                             "{%0,%1,%2,%3}, {%4,%5,%6,%7}, {%8,%9}, {%0,%1,%2,%3};"
                             : "+f"(c0), "+f"(c1), "+f"(c2), "+f"(c3)
                             : "r"(A1[kb][0]), "r"(A1[kb][1]), "r"(A1[kb][2]), "r"(A1[kb][3]),
                               "r"(b0), "r"(b1r));
            }
            float bb0 = sb1[nt * 8 + col0], bb1 = sb1[nt * 8 + col0 + 1];
            c0 = fmaxf(c0 + bb0, 0.0f);
            c1 = fmaxf(c1 + bb1, 0.0f);
            c2 = fmaxf(c2 + bb0, 0.0f);
            c3 = fmaxf(c3 + bb1, 0.0f);
            *(__half2*)(myA + r * 72 + nt * 8 + col0) = __floats2half2_rn(c0, c1);
            *(__half2*)(myA + (r + 8) * 72 + nt * 8 + col0) = __floats2half2_rn(c2, c3);
        }
        __syncwarp();

        unsigned A2[4][4];
#pragma unroll
        for (int kb = 0; kb < 4; kb++) {
            unsigned addr = aBase + (aRow * 72 + kb * 16 + aColOfs) * 2;
            asm volatile("ldmatrix.sync.aligned.m8n8.x4.shared.b16 {%0,%1,%2,%3}, [%4];"
                         : "=r"(A2[kb][0]), "=r"(A2[kb][1]), "=r"(A2[kb][2]), "=r"(A2[kb][3])
                         : "r"(addr));
        }
        __syncwarp();

#pragma unroll
        for (int nt = 0; nt < 8; nt++) {
            float c0 = 0.f, c1 = 0.f, c2 = 0.f, c3 = 0.f;
#pragma unroll
            for (int kb = 0; kb < 4; kb++) {
                unsigned b0, b1r;
                unsigned addr = w2Base + ((nt * 8 + bRowOfs) * 72 + kb * 16 + bColOfs) * 2;
                asm volatile("ldmatrix.sync.aligned.m8n8.x2.shared.b16 {%0,%1}, [%2];"
                             : "=r"(b0), "=r"(b1r) : "r"(addr));
                asm volatile("mma.sync.aligned.m16n8k16.row.col.f32.f16.f16.f32 "
                             "{%0,%1,%2,%3}, {%4,%5,%6,%7}, {%8,%9}, {%0,%1,%2,%3};"
                             : "+f"(c0), "+f"(c1), "+f"(c2), "+f"(c3)
                             : "r"(A2[kb][0]), "r"(A2[kb][1]), "r"(A2[kb][2]), "r"(A2[kb][3]),
                               "r"(b0), "r"(b1r));
            }
            float bb0 = sb2[nt * 8 + col0], bb1 = sb2[nt * 8 + col0 + 1];
            c0 += bb0; c1 += bb1; c2 += bb0; c3 += bb1;
            *(float2*)&g_t[(size_t)(n0 + r) * NH + nt * 8 + col0] = make_float2(c0, c1);
            *(float2*)&g_t[(size_t)(n0 + r + 8) * NH + nt * 8 + col0] = make_float2(c2, c3);
            st_s[nt * 2 + 0] += c0 + c2;
            st_q[nt * 2 + 0] += c0 * c0 + c2 * c2;
            st_s[nt * 2 + 1] += c1 + c3;
            st_q[nt * 2 + 1] += c1 * c1 + c3 * c3;
        }
        __syncwarp();
    }

#pragma unroll
    for (int i = 0; i < 16; i++) {
#pragma unroll
        for (int o = 4; o < 32; o <<= 1) {
            st_s[i] += __shfl_xor_sync(0xFFFFFFFFu, st_s[i], o);
            st_q[i] += __shfl_xor_sync(0xFFFFFFFFu, st_q[i], o);
        }
    }
    if (lane < 4) {
#pragma unroll
        for (int nt = 0; nt < 8; nt++) {
#pragma unroll
            for (int i = 0; i < 2; i++) {
                int col = nt * 8 + lane * 2 + i;
                atomicAdd(&ssum[col], st_s[nt * 2 + i]);
                atomicAdd(&ssq[col], st_q[nt * 2 + i]);
            }
        }
    }
    __syncthreads();
    if (tid < NH) {
        atomicAdd(&g_stats[l][tid], ssum[tid]);
        atomicAdd(&g_stats[l][NH + tid], ssq[tid]);
    }
}

// ---------------------------------------------------------------------------
// BN apply + ReLU: g_t -> g_h (fp32) + g_hh (fp16 mirror)
// ---------------------------------------------------------------------------
__global__ void bn_kernel(const float* __restrict__ gamma,
                          const float* __restrict__ beta, int l) {
    __shared__ float sc[NH], sh[NH];
    int tid = threadIdx.x;
    if (tid < NH) {
        float m = g_stats[l][tid] * (1.0f / NN);
        float v = g_stats[l][NH + tid] * (1.0f / NN) - m * m;
        float inv = rsqrtf(v + BN_EPS);
        float s = inv * __ldg(gamma + tid);
        sc[tid] = s;
        sh[tid] = __ldg(beta + tid) - m * s;
    }
    __syncthreads();
    for (int i = blockIdx.x * blockDim.x + tid; i < NN * NH / 4;
         i += gridDim.x * blockDim.x) {
        int c4 = (i & (NH / 4 - 1)) * 4;
        float4 v = ((const float4*)g_t)[i];
        v.x = fmaxf(v.x * sc[c4 + 0] + sh[c4 + 0], 0.0f);
        v.y = fmaxf(v.y * sc[c4 + 1] + sh[c4 + 1], 0.0f);
        v.z = fmaxf(v.z * sc[c4 + 2] + sh[c4 + 2], 0.0f);
        v.w = fmaxf(v.w * sc[c4 + 3] + sh[c4 + 3], 0.0f);
        ((float4*)g_h)[i] = v;
        __half2 lo = __floats2half2_rn(v.x, v.y);
        __half2 hi = __floats2half2_rn(v.z, v.w);
        uint2 u;
        u.x = *(unsigned*)&lo;
        u.y = *(unsigned*)&hi;
        *(uint2*)&g_hh[i * 2] = u;
    }
}

// ---------------------------------------------------------------------------
__global__ void pool_kernel(const int* __restrict__ batch,
                            const float* __restrict__ gam_p,
                            const float* __restrict__ bet_p) {
    __shared__ float ssc[NH], ssh[NH];
    int tid = threadIdx.x;
    if (tid < NH) {
        float m = g_stats[NL - 1][tid] * (1.0f / NN);
        float v = g_stats[NL - 1][NH + tid] * (1.0f / NN) - m * m;
        float s = rsqrtf(v + BN_EPS) * __ldg(gam_p + tid);
        ssc[tid] = s;
        ssh[tid] = __ldg(bet_p + tid) - m * s;
    }
    __syncthreads();
    int gid = blockIdx.x * blockDim.x + tid;
    int n = gid >> 4;
    if (n >= NN) return;
    int q = (gid & 15) << 2;
    int g = __ldg(batch + n);
    float4 v = *(const float4*)(g_t + (size_t)n * NH + q);
    v.x = fmaxf(v.x * ssc[q + 0] + ssh[q + 0], 0.0f);
    v.y = fmaxf(v.y * ssc[q + 1] + ssh[q + 1], 0.0f);
    v.z = fmaxf(v.z * ssc[q + 2] + ssh[q + 2], 0.0f);
    v.w = fmaxf(v.w * ssc[q + 3] + ssh[q + 3], 0.0f);
    float* p = g_pool + (size_t)g * NH + q;
    asm volatile("red.global.add.v4.f32 [%0], {%1,%2,%3,%4};"
                 :: "l"(p), "f"(v.x), "f"(v.y), "f"(v.z), "f"(v.w)
                 : "memory");
    if (q == 0) atomicAdd(&g_cnt[g], 1.0f);
}

// ---------------------------------------------------------------------------
// Final classifier + tail cleanup.
// ---------------------------------------------------------------------------
__global__ void final_kernel(const float* __restrict__ lw,
                             const float* __restrict__ lb,
                             float* __restrict__ out) {
    __shared__ float sp[NH];
    int g = blockIdx.x, tid = threadIdx.x;
    float cnt = fmaxf(g_cnt[g], 1.0f);
    if (tid < NH) sp[tid] = g_pool[g * NH + tid] / cnt;
    __syncthreads();
    if (tid < NC) {
        float acc = __ldg(lb + tid);
        for (int k = 0; k < NH; k++) acc += sp[k] * __ldg(lw + k * NC + tid);
        out[g * NC + tid] = acc;
    }

    // ---- tail cleanup (own slices only) ----
    if (tid < NH) g_pool[g * NH + tid] = 0.0f;
    if (tid == 0) g_cnt[g] = 0.0f;
    for (int i = g * 64 + tid; i < NN; i += NG * 64) g_deg[i] = 0;
    if (g == 0) {
        if (tid == 0) g_ecnt = 0;
        for (int i = tid; i < NL * 2 * NH; i += 64) ((float*)g_stats)[i] = 0.0f;
    }
}

// ---------------------------------------------------------------------------
extern "C" void kernel_launch(void* const* d_in, const int* in_sizes, int n_in,
                              void* d_out, int out_size) {
    const float* x     = (const float*)d_in[0];
    const int*   ei    = (const int*)d_in[1];
    const int*   batch = (const int*)d_in[2];
    const float* enc_w = (const float*)d_in[3];
    const float* enc_b = (const float*)d_in[4];
    const float* eps   = (const float*)d_in[5];
    const float* cw1   = (const float*)d_in[6];
    const float* cb1   = (const float*)d_in[7];
    const float* cw2   = (const float*)d_in[8];
    const float* cb2   = (const float*)d_in[9];
    const float* gam   = (const float*)d_in[10];
    const float* bet   = (const float*)d_in[11];
    const float* lw    = (const float*)d_in[12];
    const float* lb    = (const float*)d_in[13];
    float* out = (float*)d_out;

    // One-time host resources (no device memory involved)
    static cudaStream_t s_side = nullptr;
    static cudaEvent_t ev_fork = nullptr, ev_join = nullptr;
    if (s_side == nullptr) {
        cudaStreamCreateWithFlags(&s_side, cudaStreamNonBlocking);
        cudaEventCreateWithFlags(&ev_fork, cudaEventDisableTiming);
        cudaEventCreateWithFlags(&ev_join, cudaEventDisableTiming);
    }

    // Fork: CSR build on side stream, encoder on main stream (independent).
    cudaEventRecord(ev_fork, 0);
    cudaStreamWaitEvent(s_side, ev_fork, 0);

    hist_kernel<<<(NE / 4 + 255) / 256, 256, 0, s_side>>>(ei);
    scan_fused_kernel<<<SCAN_B, 256, 0, s_side>>>();
    fill_kernel<<<(NE / 4 + 255) / 256, 256, 0, s_side>>>(ei);

    enc_kernel<<<EGRID, 256>>>(x, enc_w, enc_b);

    cudaEventRecord(ev_join, s_side);
    cudaStreamWaitEvent(0, ev_join, 0);

    for (int l = 0; l < NL; l++) {
        layer_kernel<<<LGRID, LWARPS * 32>>>(eps + l, l,
                                             cw1 + (size_t)l * NH * NH, cb1 + l * NH,
                                             cw2 + (size_t)l * NH * NH, cb2 + l * NH);
        if (l < NL - 1)
            bn_kernel<<<444, 256>>>(gam + l * NH, bet + l * NH, l);
    }

    pool_kernel<<<(NN * 16 + 255) / 256, 256>>>(batch, gam + 2 * NH, bet + 2 * NH);
    final_kernel<<<NG, 64>>>(lw, lb, out);
}

// round 15
// speedup vs baseline: 1.1931x; 1.1931x over previous
#include <cuda_runtime.h>
#include <cuda_fp16.h>

#define NN 50000
#define NE 800000
#define NF 128
#define NH 64
#define NL 3
#define NG 512
#define NC 10
#define SCAN_B 196   // ceil(50000/256)
#define BN_EPS 1e-5f
#define NTILE 3125   // 50000 / 16
#define EGRID 391    // enc: 8 warps/block, 1 tile per warp
#define LWARPS 4     // layer: warps per block
#define LGRID 782    // ceil(3125/4) -> 1 tile per warp, 4-warp blocks

// Scratch (no allocations allowed). All zero-initialized at module load;
// final_kernel re-zeroes the mutable ones at the END of every launch.
__device__ float g_h[NN * NH];            // node features fp32 (post BN+ReLU)
__device__ unsigned g_hh[NN * NH / 2];    // fp16x2 mirror (neighbor reads)
__device__ float g_t[NN * NH];            // raw MLP output (pre-BN)
__device__ float g_stats[NL][2 * NH];
__device__ float g_pool[NG * NH];
__device__ float g_cnt[NG];
// CSR scratch
__device__ int g_deg[NN];
__device__ int g_off[NN];
__device__ int g_rank[NE];
__device__ int g_csr[NE];
__device__ int g_ecnt;

__device__ __forceinline__ unsigned smem_u32(const void* p) {
    unsigned a;
    asm("{ .reg .u64 t; cvta.to.shared.u64 t, %1; cvt.u32.u64 %0, t; }"
        : "=r"(a) : "l"(p));
    return a;
}

// ---------------------------------------------------------------------------
// hist + per-edge rank (atomic return reused -> atomic-free fill).
// Requires g_deg == 0 on entry (guaranteed by tail cleanup / static init).
// ---------------------------------------------------------------------------
__global__ void hist_kernel(const int* __restrict__ ei) {
    int t = blockIdx.x * blockDim.x + threadIdx.x;
    if (t >= NE / 4) return;
    int4 d = ((const int4*)(ei + NE))[t];
    int4 r;
    r.x = atomicAdd(&g_deg[d.x], 1);
    r.y = atomicAdd(&g_deg[d.y], 1);
    r.z = atomicAdd(&g_deg[d.z], 1);
    r.w = atomicAdd(&g_deg[d.w], 1);
    ((int4*)g_rank)[t] = r;
}

__global__ void scan_fused_kernel() {
    __shared__ int s[256];
    __shared__ int sbase;
    int tid = threadIdx.x, i = blockIdx.x * 256 + tid;
    int v = (i < NN) ? g_deg[i] : 0;
    s[tid] = v;
    __syncthreads();
#pragma unroll
    for (int d = 1; d < 256; d <<= 1) {
        int t = (tid >= d) ? s[tid - d] : 0;
        __syncthreads();
        s[tid] += t;
        __syncthreads();
    }
    if (tid == 255) sbase = atomicAdd(&g_ecnt, s[255]);
    __syncthreads();
    if (i < NN) g_off[i] = sbase + s[tid] - v;
}

__global__ void fill_kernel(const int* __restrict__ ei) {
    int t = blockIdx.x * blockDim.x + threadIdx.x;
    if (t >= NE / 4) return;
    int4 s = ((const int4*)ei)[t];
    int4 d = ((const int4*)(ei + NE))[t];
    int4 r = ((const int4*)g_rank)[t];
    g_csr[__ldg(&g_off[d.x]) + r.x] = s.x;
    g_csr[__ldg(&g_off[d.y]) + r.y] = s.y;
    g_csr[__ldg(&g_off[d.z]) + r.z] = s.z;
    g_csr[__ldg(&g_off[d.w]) + r.w] = s.w;
}

// ---------------------------------------------------------------------------
// Tensor-core encoder: h = x @ enc_w + enc_b -> g_h + g_hh mirror.
// ---------------------------------------------------------------------------
__global__ void enc_kernel(const float* __restrict__ x,
                           const float* __restrict__ w,
                           const float* __restrict__ b) {
    __shared__ __align__(16) __half sWe[2][NH * 72];
    __shared__ __align__(16) __half sA[8][16 * 72];
    __shared__ float sbb[NH];
    int tid = threadIdx.x, wid = tid >> 5, lane = tid & 31;
    int half_ = lane >> 4, lane16 = lane & 15;
    __half* hh = (__half*)g_hh;

    for (int i = tid; i < NF * NH; i += 256) {
        int k = i >> 6, n = i & 63;
        sWe[k >> 6][n * 72 + (k & 63)] = __float2half_rn(w[i]);
    }
    if (tid < NH) sbb[tid] = __ldg(b + tid);
    __syncthreads();

    __half* myA = sA[wid];
    unsigned aBase = smem_u32(myA);
    unsigned wBase0 = smem_u32(sWe[0]);
    unsigned wBase1 = smem_u32(sWe[1]);

    int aRow = lane & 15;
    int aColOfs = (lane >= 16) ? 8 : 0;
    int bRowOfs = lane & 7;
    int bColOfs = (lane & 8) ? 8 : 0;
    int col0 = (lane & 3) * 2;
    int r = lane >> 2;

    for (int wt = blockIdx.x * 8 + wid; wt < NTILE; wt += gridDim.x * 8) {
        int n0 = wt * 16;
        float c[8][4];
#pragma unroll
        for (int nt = 0; nt < 8; nt++)
#pragma unroll
            for (int i = 0; i < 4; i++) c[nt][i] = 0.0f;

#pragma unroll
        for (int h = 0; h < 2; h++) {
#pragma unroll
            for (int p = 0; p < 8; p++) {
                int row = p * 2 + half_;
                float4 v = *(const float4*)(x + (size_t)(n0 + row) * NF + h * 64 + lane16 * 4);
                __half2 lo = __floats2half2_rn(v.x, v.y);
                __half2 hi = __floats2half2_rn(v.z, v.w);
                uint2 u;
                u.x = *(unsigned*)&lo;
                u.y = *(unsigned*)&hi;
                *(uint2*)(myA + row * 72 + lane16 * 4) = u;
            }
            __syncwarp();

            unsigned A[4][4];
#pragma unroll
            for (int kb = 0; kb < 4; kb++) {
                unsigned addr = aBase + (aRow * 72 + kb * 16 + aColOfs) * 2;
                asm volatile("ldmatrix.sync.aligned.m8n8.x4.shared.b16 {%0,%1,%2,%3}, [%4];"
                             : "=r"(A[kb][0]), "=r"(A[kb][1]), "=r"(A[kb][2]), "=r"(A[kb][3])
                             : "r"(addr));
            }
            unsigned wBase = h ? wBase1 : wBase0;
#pragma unroll
            for (int nt = 0; nt < 8; nt++) {
#pragma unroll
                for (int kb = 0; kb < 4; kb++) {
                    unsigned b0, b1r;
                    unsigned addr = wBase + ((nt * 8 + bRowOfs) * 72 + kb * 16 + bColOfs) * 2;
                    asm volatile("ldmatrix.sync.aligned.m8n8.x2.shared.b16 {%0,%1}, [%2];"
                                 : "=r"(b0), "=r"(b1r) : "r"(addr));
                    asm volatile("mma.sync.aligned.m16n8k16.row.col.f32.f16.f16.f32 "
                                 "{%0,%1,%2,%3}, {%4,%5,%6,%7}, {%8,%9}, {%0,%1,%2,%3};"
                                 : "+f"(c[nt][0]), "+f"(c[nt][1]), "+f"(c[nt][2]), "+f"(c[nt][3])
                                 : "r"(A[kb][0]), "r"(A[kb][1]), "r"(A[kb][2]), "r"(A[kb][3]),
                                   "r"(b0), "r"(b1r));
                }
            }
            __syncwarp();
        }

#pragma unroll
        for (int nt = 0; nt < 8; nt++) {
            float bb0 = sbb[nt * 8 + col0], bb1 = sbb[nt * 8 + col0 + 1];
            float c0 = c[nt][0] + bb0, c1 = c[nt][1] + bb1;
            float c2 = c[nt][2] + bb0, c3 = c[nt][3] + bb1;
            size_t i0 = (size_t)(n0 + r) * NH + nt * 8 + col0;
            size_t i1 = (size_t)(n0 + r + 8) * NH + nt * 8 + col0;
            *(float2*)&g_h[i0] = make_float2(c0, c1);
            *(float2*)&g_h[i1] = make_float2(c2, c3);
            *(__half2*)&hh[i0] = __floats2half2_rn(c0, c1);
            *(__half2*)&hh[i1] = __floats2half2_rn(c2, c3);
        }
    }
}

// ---------------------------------------------------------------------------
// Fused layer via tensor cores. 128 threads (4 warps) per block, smem ~29KB
// -> ~5 blocks/SM (20 warps). Gather: half-warp per node, uint2 loads.
// ---------------------------------------------------------------------------
__global__ void layer_kernel(const float* __restrict__ epsl, int l,
                             const float* __restrict__ w1, const float* __restrict__ b1,
                             const float* __restrict__ w2, const float* __restrict__ b2) {
    __shared__ __align__(16) __half sW1[NH * 72];
    __shared__ __align__(16) __half sW2[NH * 72];
    __shared__ __align__(16) __half sA[LWARPS][16 * 72];
    __shared__ float sb1[NH], sb2[NH];
    __shared__ float ssum[NH], ssq[NH];

    int tid = threadIdx.x, wid = tid >> 5, lane = tid & 31;
    int half_ = lane >> 4, lane16 = lane & 15;
    unsigned hmask = 0xFFFFu << (half_ * 16);

    for (int i = tid; i < NH * NH; i += LWARPS * 32) {
        int k = i >> 6, n = i & 63;
        sW1[n * 72 + k] = __float2half_rn(w1[i]);
        sW2[n * 72 + k] = __float2half_rn(w2[i]);
    }
    if (tid < NH) {
        sb1[tid] = __ldg(b1 + tid);
        sb2[tid] = __ldg(b2 + tid);
        ssum[tid] = 0.0f; ssq[tid] = 0.0f;
    }
    __syncthreads();

    float se = 1.0f + __ldg(epsl);
    __half* myA = sA[wid];
    unsigned aBase = smem_u32(myA);
    unsigned w1Base = smem_u32(sW1);
    unsigned w2Base = smem_u32(sW2);

    int aRow = lane & 15;
    int aColOfs = (lane >= 16) ? 8 : 0;
    int bRowOfs = lane & 7;
    int bColOfs = (lane & 8) ? 8 : 0;
    int col0 = (lane & 3) * 2;
    int r = lane >> 2;

    float st_s[16], st_q[16];
#pragma unroll
    for (int i = 0; i < 16; i++) { st_s[i] = 0.0f; st_q[i] = 0.0f; }

    for (int wt = blockIdx.x * LWARPS + wid; wt < NTILE; wt += gridDim.x * LWARPS) {
        int n0 = wt * 16;
#pragma unroll 2
        for (int p = 0; p < 8; p++) {
            int node = n0 + p * 2 + half_;
            float4 acc = *(const float4*)(g_h + (size_t)node * NH + lane16 * 4);
            acc.x *= se; acc.y *= se; acc.z *= se; acc.w *= se;
            int begin = __ldg(&g_off[node]);
            int end   = begin + __ldg(&g_deg[node]);
            for (int base = begin; base < end; base += 16) {
                int cnt = min(16, end - base);
                int sidx = (lane16 < cnt) ? __ldg(&g_csr[base + lane16]) : 0;
                int j = 0;
                for (; j + 4 <= cnt; j += 4) {
                    int s0 = __shfl_sync(hmask, sidx, j + 0, 16);
                    int s1 = __shfl_sync(hmask, sidx, j + 1, 16);
                    int s2 = __shfl_sync(hmask, sidx, j + 2, 16);
                    int s3 = __shfl_sync(hmask, sidx, j + 3, 16);
                    uint2 q0 = *(const uint2*)(g_hh + (size_t)s0 * 32 + lane16 * 2);
                    uint2 q1 = *(const uint2*)(g_hh + (size_t)s1 * 32 + lane16 * 2);
                    uint2 q2 = *(const uint2*)(g_hh + (size_t)s2 * 32 + lane16 * 2);
                    uint2 q3 = *(const uint2*)(g_hh + (size_t)s3 * 32 + lane16 * 2);
                    float2 f;
                    f = __half22float2(*(__half2*)&q0.x); acc.x += f.x; acc.y += f.y;
                    f = __half22float2(*(__half2*)&q0.y); acc.z += f.x; acc.w += f.y;
                    f = __half22float2(*(__half2*)&q1.x); acc.x += f.x; acc.y += f.y;
                    f = __half22float2(*(__half2*)&q1.y); acc.z += f.x; acc.w += f.y;
                    f = __half22float2(*(__half2*)&q2.x); acc.x += f.x; acc.y += f.y;
                    f = __half22float2(*(__half2*)&q2.y); acc.z += f.x; acc.w += f.y;
                    f = __half22float2(*(__half2*)&q3.x); acc.x += f.x; acc.y += f.y;
                    f = __half22float2(*(__half2*)&q3.y); acc.z += f.x; acc.w += f.y;
                }
                for (; j < cnt; j++) {
                    int s0 = __shfl_sync(hmask, sidx, j, 16);
                    uint2 q0 = *(const uint2*)(g_hh + (size_t)s0 * 32 + lane16 * 2);
                    float2 f;
                    f = __half22float2(*(__half2*)&q0.x); acc.x += f.x; acc.y += f.y;
                    f = __half22float2(*(__half2*)&q0.y); acc.z += f.x; acc.w += f.y;
                }
            }
            __half2 h01 = __floats2half2_rn(acc.x, acc.y);
            __half2 h23 = __floats2half2_rn(acc.z, acc.w);
            uint2 u;
            u.x = *(unsigned*)&h01;
            u.y = *(unsigned*)&h23;
            *(uint2*)(myA + (p * 2 + half_) * 72 + lane16 * 4) = u;
        }
        __syncwarp();

        unsigned A1[4][4];
#pragma unroll
        for (int kb = 0; kb < 4; kb++) {
            unsigned addr = aBase + (aRow * 72 + kb * 16 + aColOfs) * 2;
            asm volatile("ldmatrix.sync.aligned.m8n8.x4.shared.b16 {%0,%1,%2,%3}, [%4];"
                         : "=r"(A1[kb][0]), "=r"(A1[kb][1]), "=r"(A1[kb][2]), "=r"(A1[kb][3])
                         : "r"(addr));
        }
        __syncwarp();

#pragma unroll
        for (int nt = 0; nt < 8; nt++) {
            float c0 = 0.f, c1 = 0.f, c2 = 0.f, c3 = 0.f;
#pragma unroll
            for (int kb = 0; kb < 4; kb++) {
                unsigned b0, b1r;
                unsigned addr = w1Base + ((nt * 8 + bRowOfs) * 72 + kb * 16 + bColOfs) * 2;
                asm volatile("ldmatrix.sync.aligned.m8n8.x2.shared.b16 {%0,%1}, [%2];"
                             : "=r"(b0), "=r"(b1r) : "r"(addr));
                asm volatile("mma.sync.aligned.m16n8k16.row.col.f32.f16.f16.f32 "
                             "{%0,%1,%2,%3}, {%4,%5,%6,%7}, {%8,%9}, {%0,%1,%2,%3};"
                             : "+f"(c0), "+f"(c1), "+f"(c2), "+f"(c3)
                             : "r"(A1[kb][0]), "r"(A1[kb][1]), "r"(A1[kb][2]), "r"(A1[kb][3]),
                               "r"(b0), "r"(b1r));
            }
            float bb0 = sb1[nt * 8 + col0], bb1 = sb1[nt * 8 + col0 + 1];
            c0 = fmaxf(c0 + bb0, 0.0f);
            c1 = fmaxf(c1 + bb1, 0.0f);
            c2 = fmaxf(c2 + bb0, 0.0f);
            c3 = fmaxf(c3 + bb1, 0.0f);
            *(__half2*)(myA + r * 72 + nt * 8 + col0) = __floats2half2_rn(c0, c1);
            *(__half2*)(myA + (r + 8) * 72 + nt * 8 + col0) = __floats2half2_rn(c2, c3);
        }
        __syncwarp();

        unsigned A2[4][4];
#pragma unroll
        for (int kb = 0; kb < 4; kb++) {
            unsigned addr = aBase + (aRow * 72 + kb * 16 + aColOfs) * 2;
            asm volatile("ldmatrix.sync.aligned.m8n8.x4.shared.b16 {%0,%1,%2,%3}, [%4];"
                         : "=r"(A2[kb][0]), "=r"(A2[kb][1]), "=r"(A2[kb][2]), "=r"(A2[kb][3])
                         : "r"(addr));
        }
        __syncwarp();

#pragma unroll
        for (int nt = 0; nt < 8; nt++) {
            float c0 = 0.f, c1 = 0.f, c2 = 0.f, c3 = 0.f;
#pragma unroll
            for (int kb = 0; kb < 4; kb++) {
                unsigned b0, b1r;
                unsigned addr = w2Base + ((nt * 8 + bRowOfs) * 72 + kb * 16 + bColOfs) * 2;
                asm volatile("ldmatrix.sync.aligned.m8n8.x2.shared.b16 {%0,%1}, [%2];"
                             : "=r"(b0), "=r"(b1r) : "r"(addr));
                asm volatile("mma.sync.aligned.m16n8k16.row.col.f32.f16.f16.f32 "
                             "{%0,%1,%2,%3}, {%4,%5,%6,%7}, {%8,%9}, {%0,%1,%2,%3};"
                             : "+f"(c0), "+f"(c1), "+f"(c2), "+f"(c3)
                             : "r"(A2[kb][0]), "r"(A2[kb][1]), "r"(A2[kb][2]), "r"(A2[kb][3]),
                               "r"(b0), "r"(b1r));
            }
            float bb0 = sb2[nt * 8 + col0], bb1 = sb2[nt * 8 + col0 + 1];
            c0 += bb0; c1 += bb1; c2 += bb0; c3 += bb1;
            *(float2*)&g_t[(size_t)(n0 + r) * NH + nt * 8 + col0] = make_float2(c0, c1);
            *(float2*)&g_t[(size_t)(n0 + r + 8) * NH + nt * 8 + col0] = make_float2(c2, c3);
            st_s[nt * 2 + 0] += c0 + c2;
            st_q[nt * 2 + 0] += c0 * c0 + c2 * c2;
            st_s[nt * 2 + 1] += c1 + c3;
            st_q[nt * 2 + 1] += c1 * c1 + c3 * c3;
        }
        __syncwarp();
    }

#pragma unroll
    for (int i = 0; i < 16; i++) {
#pragma unroll
        for (int o = 4; o < 32; o <<= 1) {
            st_s[i] += __shfl_xor_sync(0xFFFFFFFFu, st_s[i], o);
            st_q[i] += __shfl_xor_sync(0xFFFFFFFFu, st_q[i], o);
        }
    }
    if (lane < 4) {
#pragma unroll
        for (int nt = 0; nt < 8; nt++) {
#pragma unroll
            for (int i = 0; i < 2; i++) {
                int col = nt * 8 + lane * 2 + i;
                atomicAdd(&ssum[col], st_s[nt * 2 + i]);
                atomicAdd(&ssq[col], st_q[nt * 2 + i]);
            }
        }
    }
    __syncthreads();
    if (tid < NH) {
        atomicAdd(&g_stats[l][tid], ssum[tid]);
        atomicAdd(&g_stats[l][NH + tid], ssq[tid]);
    }
}

// ---------------------------------------------------------------------------
// BN apply + ReLU: g_t -> g_h (fp32) + g_hh (fp16 mirror)
// ---------------------------------------------------------------------------
__global__ void bn_kernel(const float* __restrict__ gamma,
                          const float* __restrict__ beta, int l) {
    __shared__ float sc[NH], sh[NH];
    int tid = threadIdx.x;
    if (tid < NH) {
        float m = g_stats[l][tid] * (1.0f / NN);
        float v = g_stats[l][NH + tid] * (1.0f / NN) - m * m;
        float inv = rsqrtf(v + BN_EPS);
        float s = inv * __ldg(gamma + tid);
        sc[tid] = s;
        sh[tid] = __ldg(beta + tid) - m * s;
    }
    __syncthreads();
    for (int i = blockIdx.x * blockDim.x + tid; i < NN * NH / 4;
         i += gridDim.x * blockDim.x) {
        int c4 = (i & (NH / 4 - 1)) * 4;
        float4 v = ((const float4*)g_t)[i];
        v.x = fmaxf(v.x * sc[c4 + 0] + sh[c4 + 0], 0.0f);
        v.y = fmaxf(v.y * sc[c4 + 1] + sh[c4 + 1], 0.0f);
        v.z = fmaxf(v.z * sc[c4 + 2] + sh[c4 + 2], 0.0f);
        v.w = fmaxf(v.w * sc[c4 + 3] + sh[c4 + 3], 0.0f);
        ((float4*)g_h)[i] = v;
        __half2 lo = __floats2half2_rn(v.x, v.y);
        __half2 hi = __floats2half2_rn(v.z, v.w);
        uint2 u;
        u.x = *(unsigned*)&lo;
        u.y = *(unsigned*)&hi;
        *(uint2*)&g_hh[i * 2] = u;
    }
}

// ---------------------------------------------------------------------------
__global__ void pool_kernel(const int* __restrict__ batch,
                            const float* __restrict__ gam_p,
                            const float* __restrict__ bet_p) {
    __shared__ float ssc[NH], ssh[NH];
    int tid = threadIdx.x;
    if (tid < NH) {
        float m = g_stats[NL - 1][tid] * (1.0f / NN);
        float v = g_stats[NL - 1][NH + tid] * (1.0f / NN) - m * m;
        float s = rsqrtf(v + BN_EPS) * __ldg(gam_p + tid);
        ssc[tid] = s;
        ssh[tid] = __ldg(bet_p + tid) - m * s;
    }
    __syncthreads();
    int gid = blockIdx.x * blockDim.x + tid;
    int n = gid >> 4;
    if (n >= NN) return;
    int q = (gid & 15) << 2;
    int g = __ldg(batch + n);
    float4 v = *(const float4*)(g_t + (size_t)n * NH + q);
    v.x = fmaxf(v.x * ssc[q + 0] + ssh[q + 0], 0.0f);
    v.y = fmaxf(v.y * ssc[q + 1] + ssh[q + 1], 0.0f);
    v.z = fmaxf(v.z * ssc[q + 2] + ssh[q + 2], 0.0f);
    v.w = fmaxf(v.w * ssc[q + 3] + ssh[q + 3], 0.0f);
    float* p = g_pool + (size_t)g * NH + q;
    asm volatile("red.global.add.v4.f32 [%0], {%1,%2,%3,%4};"
                 :: "l"(p), "f"(v.x), "f"(v.y), "f"(v.z), "f"(v.w)
                 : "memory");
    if (q == 0) atomicAdd(&g_cnt[g], 1.0f);
}

// ---------------------------------------------------------------------------
// Final classifier + tail cleanup.
// ---------------------------------------------------------------------------
__global__ void final_kernel(const float* __restrict__ lw,
                             const float* __restrict__ lb,
                             float* __restrict__ out) {
    __shared__ float sp[NH];
    int g = blockIdx.x, tid = threadIdx.x;
    float cnt = fmaxf(g_cnt[g], 1.0f);
    if (tid < NH) sp[tid] = g_pool[g * NH + tid] / cnt;
    __syncthreads();
    if (tid < NC) {
        float acc = __ldg(lb + tid);
        for (int k = 0; k < NH; k++) acc += sp[k] * __ldg(lw + k * NC + tid);
        out[g * NC + tid] = acc;
    }

    // ---- tail cleanup (own slices only) ----
    if (tid < NH) g_pool[g * NH + tid] = 0.0f;
    if (tid == 0) g_cnt[g] = 0.0f;
    for (int i = g * 64 + tid; i < NN; i += NG * 64) g_deg[i] = 0;
    if (g == 0) {
        if (tid == 0) g_ecnt = 0;
        for (int i = tid; i < NL * 2 * NH; i += 64) ((float*)g_stats)[i] = 0.0f;
    }
}

// ---------------------------------------------------------------------------
extern "C" void kernel_launch(void* const* d_in, const int* in_sizes, int n_in,
                              void* d_out, int out_size) {
    const float* x     = (const float*)d_in[0];
    const int*   ei    = (const int*)d_in[1];
    const int*   batch = (const int*)d_in[2];
    const float* enc_w = (const float*)d_in[3];
    const float* enc_b = (const float*)d_in[4];
    const float* eps   = (const float*)d_in[5];
    const float* cw1   = (const float*)d_in[6];
    const float* cb1   = (const float*)d_in[7];
    const float* cw2   = (const float*)d_in[8];
    const float* cb2   = (const float*)d_in[9];
    const float* gam   = (const float*)d_in[10];
    const float* bet   = (const float*)d_in[11];
    const float* lw    = (const float*)d_in[12];
    const float* lb    = (const float*)d_in[13];
    float* out = (float*)d_out;

    // One-time host resources (no device memory involved)
    static cudaStream_t s_side = nullptr;
    static cudaEvent_t ev_fork = nullptr, ev_join = nullptr;
    if (s_side == nullptr) {
        cudaStreamCreateWithFlags(&s_side, cudaStreamNonBlocking);
        cudaEventCreateWithFlags(&ev_fork, cudaEventDisableTiming);
        cudaEventCreateWithFlags(&ev_join, cudaEventDisableTiming);
    }

    // Fork: CSR build on side stream, encoder on main stream (independent).
    cudaEventRecord(ev_fork, 0);
    cudaStreamWaitEvent(s_side, ev_fork, 0);

    hist_kernel<<<(NE / 4 + 255) / 256, 256, 0, s_side>>>(ei);
    scan_fused_kernel<<<SCAN_B, 256, 0, s_side>>>();
    fill_kernel<<<(NE / 4 + 255) / 256, 256, 0, s_side>>>(ei);

    enc_kernel<<<EGRID, 256>>>(x, enc_w, enc_b);

    cudaEventRecord(ev_join, s_side);
    cudaStreamWaitEvent(0, ev_join, 0);

    for (int l = 0; l < NL; l++) {
        layer_kernel<<<LGRID, LWARPS * 32>>>(eps + l, l,
                                             cw1 + (size_t)l * NH * NH, cb1 + l * NH,
                                             cw2 + (size_t)l * NH * NH, cb2 + l * NH);
        if (l < NL - 1)
            bn_kernel<<<444, 256>>>(gam + l * NH, bet + l * NH, l);
    }

    pool_kernel<<<(NN * 16 + 255) / 256, 256>>>(batch, gam + 2 * NH, bet + 2 * NH);
    final_kernel<<<NG, 64>>>(lw, lb, out);
}

// round 17
// speedup vs baseline: 1.2017x; 1.0072x over previous
#include <cuda_runtime.h>
#include <cuda_fp16.h>

#define NN 50000
#define NE 800000
#define NF 128
#define NH 64
#define NL 3
#define NG 512
#define NC 10
#define SCAN_B 196   // ceil(50000/256)
#define BN_EPS 1e-5f
#define NTILE 3125   // 50000 / 16
#define EGRID 391    // enc: 8 warps/block, 1 tile per warp
#define LWARPS 4     // layer: warps per block
#define LGRID 782    // ceil(3125/4) -> 1 tile per warp, 4-warp blocks

// Scratch (no allocations allowed). All zero-initialized at module load.
// Cleanup protocol (deterministic across graph replays):
//   g_deg   : zeroed at tail by poolfinal_kernel (poolfinal never reads deg)
//   g_stats : zeroed at head by hist_kernel block 0 (side stream, strictly
//             before any layer_kernel writes stats; hist never reads stats)
//   g_ecnt  : zeroed at head by hist_kernel block 0 (scan runs after hist)
__device__ float g_h[NN * NH];            // node features fp32 (post BN+ReLU)
__device__ unsigned g_hh[NN * NH / 2];    // fp16x2 mirror (neighbor reads)
__device__ float g_t[NN * NH];            // raw MLP output (pre-BN)
__device__ float g_stats[NL][2 * NH];
// CSR scratch
__device__ int g_deg[NN];
__device__ int g_off[NN];
__device__ int g_rank[NE];
__device__ int g_csr[NE];
__device__ int g_ecnt;

__device__ __forceinline__ unsigned smem_u32(const void* p) {
    unsigned a;
    asm("{ .reg .u64 t; cvta.to.shared.u64 t, %1; cvt.u32.u64 %0, t; }"
        : "=r"(a) : "l"(p));
    return a;
}

// ---------------------------------------------------------------------------
// hist + per-edge rank. Block 0 additionally zeroes g_stats and g_ecnt
// (safe: nothing on either stream reads them before the layer loop / scan).
// Requires g_deg == 0 on entry (poolfinal tail cleanup / static init).
// ---------------------------------------------------------------------------
__global__ void hist_kernel(const int* __restrict__ ei) {
    if (blockIdx.x == 0) {
        for (int i = threadIdx.x; i < NL * 2 * NH; i += 256)
            ((float*)g_stats)[i] = 0.0f;
        if (threadIdx.x == 0) g_ecnt = 0;
    }
    int t = blockIdx.x * blockDim.x + threadIdx.x;
    if (t >= NE / 4) return;
    int4 d = ((const int4*)(ei + NE))[t];
    int4 r;
    r.x = atomicAdd(&g_deg[d.x], 1);
    r.y = atomicAdd(&g_deg[d.y], 1);
    r.z = atomicAdd(&g_deg[d.z], 1);
    r.w = atomicAdd(&g_deg[d.w], 1);
    ((int4*)g_rank)[t] = r;
}

__global__ void scan_fused_kernel() {
    __shared__ int s[256];
    __shared__ int sbase;
    int tid = threadIdx.x, i = blockIdx.x * 256 + tid;
    int v = (i < NN) ? g_deg[i] : 0;
    s[tid] = v;
    __syncthreads();
#pragma unroll
    for (int d = 1; d < 256; d <<= 1) {
        int t = (tid >= d) ? s[tid - d] : 0;
        __syncthreads();
        s[tid] += t;
        __syncthreads();
    }
    if (tid == 255) sbase = atomicAdd(&g_ecnt, s[255]);
    __syncthreads();
    if (i < NN) g_off[i] = sbase + s[tid] - v;
}

__global__ void fill_kernel(const int* __restrict__ ei) {
    int t = blockIdx.x * blockDim.x + threadIdx.x;
    if (t >= NE / 4) return;
    int4 s = ((const int4*)ei)[t];
    int4 d = ((const int4*)(ei + NE))[t];
    int4 r = ((const int4*)g_rank)[t];
    g_csr[__ldg(&g_off[d.x]) + r.x] = s.x;
    g_csr[__ldg(&g_off[d.y]) + r.y] = s.y;
    g_csr[__ldg(&g_off[d.z]) + r.z] = s.z;
    g_csr[__ldg(&g_off[d.w]) + r.w] = s.w;
}

// ---------------------------------------------------------------------------
// Tensor-core encoder: h = x @ enc_w + enc_b -> g_h + g_hh mirror.
// ---------------------------------------------------------------------------
__global__ void enc_kernel(const float* __restrict__ x,
                           const float* __restrict__ w,
                           const float* __restrict__ b) {
    __shared__ __align__(16) __half sWe[2][NH * 72];
    __shared__ __align__(16) __half sA[8][16 * 72];
    __shared__ float sbb[NH];
    int tid = threadIdx.x, wid = tid >> 5, lane = tid & 31;
    int half_ = lane >> 4, lane16 = lane & 15;
    __half* hh = (__half*)g_hh;

    for (int i = tid; i < NF * NH; i += 256) {
        int k = i >> 6, n = i & 63;
        sWe[k >> 6][n * 72 + (k & 63)] = __float2half_rn(w[i]);
    }
    if (tid < NH) sbb[tid] = __ldg(b + tid);
    __syncthreads();

    __half* myA = sA[wid];
    unsigned aBase = smem_u32(myA);
    unsigned wBase0 = smem_u32(sWe[0]);
    unsigned wBase1 = smem_u32(sWe[1]);

    int aRow = lane & 15;
    int aColOfs = (lane >= 16) ? 8 : 0;
    int bRowOfs = lane & 7;
    int bColOfs = (lane & 8) ? 8 : 0;
    int col0 = (lane & 3) * 2;
    int r = lane >> 2;

    for (int wt = blockIdx.x * 8 + wid; wt < NTILE; wt += gridDim.x * 8) {
        int n0 = wt * 16;
        float c[8][4];
#pragma unroll
        for (int nt = 0; nt < 8; nt++)
#pragma unroll
            for (int i = 0; i < 4; i++) c[nt][i] = 0.0f;

#pragma unroll
        for (int h = 0; h < 2; h++) {
#pragma unroll
            for (int p = 0; p < 8; p++) {
                int row = p * 2 + half_;
                float4 v = *(const float4*)(x + (size_t)(n0 + row) * NF + h * 64 + lane16 * 4);
                __half2 lo = __floats2half2_rn(v.x, v.y);
                __half2 hi = __floats2half2_rn(v.z, v.w);
                uint2 u;
                u.x = *(unsigned*)&lo;
                u.y = *(unsigned*)&hi;
                *(uint2*)(myA + row * 72 + lane16 * 4) = u;
            }
            __syncwarp();

            unsigned A[4][4];
#pragma unroll
            for (int kb = 0; kb < 4; kb++) {
                unsigned addr = aBase + (aRow * 72 + kb * 16 + aColOfs) * 2;
                asm volatile("ldmatrix.sync.aligned.m8n8.x4.shared.b16 {%0,%1,%2,%3}, [%4];"
                             : "=r"(A[kb][0]), "=r"(A[kb][1]), "=r"(A[kb][2]), "=r"(A[kb][3])
                             : "r"(addr));
            }
            unsigned wBase = h ? wBase1 : wBase0;
#pragma unroll
            for (int nt = 0; nt < 8; nt++) {
#pragma unroll
                for (int kb = 0; kb < 4; kb++) {
                    unsigned b0, b1r;
                    unsigned addr = wBase + ((nt * 8 + bRowOfs) * 72 + kb * 16 + bColOfs) * 2;
                    asm volatile("ldmatrix.sync.aligned.m8n8.x2.shared.b16 {%0,%1}, [%2];"
                                 : "=r"(b0), "=r"(b1r) : "r"(addr));
                    asm volatile("mma.sync.aligned.m16n8k16.row.col.f32.f16.f16.f32 "
                                 "{%0,%1,%2,%3}, {%4,%5,%6,%7}, {%8,%9}, {%0,%1,%2,%3};"
                                 : "+f"(c[nt][0]), "+f"(c[nt][1]), "+f"(c[nt][2]), "+f"(c[nt][3])
                                 : "r"(A[kb][0]), "r"(A[kb][1]), "r"(A[kb][2]), "r"(A[kb][3]),
                                   "r"(b0), "r"(b1r));
                }
            }
            __syncwarp();
        }

#pragma unroll
        for (int nt = 0; nt < 8; nt++) {
            float bb0 = sbb[nt * 8 + col0], bb1 = sbb[nt * 8 + col0 + 1];
            float c0 = c[nt][0] + bb0, c1 = c[nt][1] + bb1;
            float c2 = c[nt][2] + bb0, c3 = c[nt][3] + bb1;
            size_t i0 = (size_t)(n0 + r) * NH + nt * 8 + col0;
            size_t i1 = (size_t)(n0 + r + 8) * NH + nt * 8 + col0;
            *(float2*)&g_h[i0] = make_float2(c0, c1);
            *(float2*)&g_h[i1] = make_float2(c2, c3);
            *(__half2*)&hh[i0] = __floats2half2_rn(c0, c1);
            *(__half2*)&hh[i1] = __floats2half2_rn(c2, c3);
        }
    }
}

// ---------------------------------------------------------------------------
// Fused layer via tensor cores (unchanged from the 174.5 baseline).
// ---------------------------------------------------------------------------
__global__ void layer_kernel(const float* __restrict__ epsl, int l,
                             const float* __restrict__ w1, const float* __restrict__ b1,
                             const float* __restrict__ w2, const float* __restrict__ b2) {
    __shared__ __align__(16) __half sW1[NH * 72];
    __shared__ __align__(16) __half sW2[NH * 72];
    __shared__ __align__(16) __half sA[LWARPS][16 * 72];
    __shared__ float sb1[NH], sb2[NH];
    __shared__ float ssum[NH], ssq[NH];

    int tid = threadIdx.x, wid = tid >> 5, lane = tid & 31;
    int half_ = lane >> 4, lane16 = lane & 15;
    unsigned hmask = 0xFFFFu << (half_ * 16);

    for (int i = tid; i < NH * NH; i += LWARPS * 32) {
        int k = i >> 6, n = i & 63;
        sW1[n * 72 + k] = __float2half_rn(w1[i]);
        sW2[n * 72 + k] = __float2half_rn(w2[i]);
    }
    if (tid < NH) {
        sb1[tid] = __ldg(b1 + tid);
        sb2[tid] = __ldg(b2 + tid);
        ssum[tid] = 0.0f; ssq[tid] = 0.0f;
    }
    __syncthreads();

    float se = 1.0f + __ldg(epsl);
    __half* myA = sA[wid];
    unsigned aBase = smem_u32(myA);
    unsigned w1Base = smem_u32(sW1);
    unsigned w2Base = smem_u32(sW2);

    int aRow = lane & 15;
    int aColOfs = (lane >= 16) ? 8 : 0;
    int bRowOfs = lane & 7;
    int bColOfs = (lane & 8) ? 8 : 0;
    int col0 = (lane & 3) * 2;
    int r = lane >> 2;

    float st_s[16], st_q[16];
#pragma unroll
    for (int i = 0; i < 16; i++) { st_s[i] = 0.0f; st_q[i] = 0.0f; }

    for (int wt = blockIdx.x * LWARPS + wid; wt < NTILE; wt += gridDim.x * LWARPS) {
        int n0 = wt * 16;
#pragma unroll 2
        for (int p = 0; p < 8; p++) {
            int node = n0 + p * 2 + half_;
            float4 acc = *(const float4*)(g_h + (size_t)node * NH + lane16 * 4);
            acc.x *= se; acc.y *= se; acc.z *= se; acc.w *= se;
            int begin = __ldg(&g_off[node]);
            int end   = begin + __ldg(&g_deg[node]);
            for (int base = begin; base < end; base += 16) {
                int cnt = min(16, end - base);
                int sidx = (lane16 < cnt) ? __ldg(&g_csr[base + lane16]) : 0;
                int j = 0;
                for (; j + 4 <= cnt; j += 4) {
                    int s0 = __shfl_sync(hmask, sidx, j + 0, 16);
                    int s1 = __shfl_sync(hmask, sidx, j + 1, 16);
                    int s2 = __shfl_sync(hmask, sidx, j + 2, 16);
                    int s3 = __shfl_sync(hmask, sidx, j + 3, 16);
                    uint2 q0 = *(const uint2*)(g_hh + (size_t)s0 * 32 + lane16 * 2);
                    uint2 q1 = *(const uint2*)(g_hh + (size_t)s1 * 32 + lane16 * 2);
                    uint2 q2 = *(const uint2*)(g_hh + (size_t)s2 * 32 + lane16 * 2);
                    uint2 q3 = *(const uint2*)(g_hh + (size_t)s3 * 32 + lane16 * 2);
                    float2 f;
                    f = __half22float2(*(__half2*)&q0.x); acc.x += f.x; acc.y += f.y;
                    f = __half22float2(*(__half2*)&q0.y); acc.z += f.x; acc.w += f.y;
                    f = __half22float2(*(__half2*)&q1.x); acc.x += f.x; acc.y += f.y;
                    f = __half22float2(*(__half2*)&q1.y); acc.z += f.x; acc.w += f.y;
                    f = __half22float2(*(__half2*)&q2.x); acc.x += f.x; acc.y += f.y;
                    f = __half22float2(*(__half2*)&q2.y); acc.z += f.x; acc.w += f.y;
                    f = __half22float2(*(__half2*)&q3.x); acc.x += f.x; acc.y += f.y;
                    f = __half22float2(*(__half2*)&q3.y); acc.z += f.x; acc.w += f.y;
                }
                for (; j < cnt; j++) {
                    int s0 = __shfl_sync(hmask, sidx, j, 16);
                    uint2 q0 = *(const uint2*)(g_hh + (size_t)s0 * 32 + lane16 * 2);
                    float2 f;
                    f = __half22float2(*(__half2*)&q0.x); acc.x += f.x; acc.y += f.y;
                    f = __half22float2(*(__half2*)&q0.y); acc.z += f.x; acc.w += f.y;
                }
            }
            __half2 h01 = __floats2half2_rn(acc.x, acc.y);
            __half2 h23 = __floats2half2_rn(acc.z, acc.w);
            uint2 u;
            u.x = *(unsigned*)&h01;
            u.y = *(unsigned*)&h23;
            *(uint2*)(myA + (p * 2 + half_) * 72 + lane16 * 4) = u;
        }
        __syncwarp();

        unsigned A1[4][4];
#pragma unroll
        for (int kb = 0; kb < 4; kb++) {
            unsigned addr = aBase + (aRow * 72 + kb * 16 + aColOfs) * 2;
            asm volatile("ldmatrix.sync.aligned.m8n8.x4.shared.b16 {%0,%1,%2,%3}, [%4];"
                         : "=r"(A1[kb][0]), "=r"(A1[kb][1]), "=r"(A1[kb][2]), "=r"(A1[kb][3])
                         : "r"(addr));
        }
        __syncwarp();

#pragma unroll
        for (int nt = 0; nt < 8; nt++) {
            float c0 = 0.f, c1 = 0.f, c2 = 0.f, c3 = 0.f;
#pragma unroll
            for (int kb = 0; kb < 4; kb++) {
                unsigned b0, b1r;
                unsigned addr = w1Base + ((nt * 8 + bRowOfs) * 72 + kb * 16 + bColOfs) * 2;
                asm volatile("ldmatrix.sync.aligned.m8n8.x2.shared.b16 {%0,%1}, [%2];"
                             : "=r"(b0), "=r"(b1r) : "r"(addr));
                asm volatile("mma.sync.aligned.m16n8k16.row.col.f32.f16.f16.f32 "
                             "{%0,%1,%2,%3}, {%4,%5,%6,%7}, {%8,%9}, {%0,%1,%2,%3};"
                             : "+f"(c0), "+f"(c1), "+f"(c2), "+f"(c3)
                             : "r"(A1[kb][0]), "r"(A1[kb][1]), "r"(A1[kb][2]), "r"(A1[kb][3]),
                               "r"(b0), "r"(b1r));
            }
            float bb0 = sb1[nt * 8 + col0], bb1 = sb1[nt * 8 + col0 + 1];
            c0 = fmaxf(c0 + bb0, 0.0f);
            c1 = fmaxf(c1 + bb1, 0.0f);
            c2 = fmaxf(c2 + bb0, 0.0f);
            c3 = fmaxf(c3 + bb1, 0.0f);
            *(__half2*)(myA + r * 72 + nt * 8 + col0) = __floats2half2_rn(c0, c1);
            *(__half2*)(myA + (r + 8) * 72 + nt * 8 + col0) = __floats2half2_rn(c2, c3);
        }
        __syncwarp();

        unsigned A2[4][4];
#pragma unroll
        for (int kb = 0; kb < 4; kb++) {
            unsigned addr = aBase + (aRow * 72 + kb * 16 + aColOfs) * 2;
            asm volatile("ldmatrix.sync.aligned.m8n8.x4.shared.b16 {%0,%1,%2,%3}, [%4];"
                         : "=r"(A2[kb][0]), "=r"(A2[kb][1]), "=r"(A2[kb][2]), "=r"(A2[kb][3])
                         : "r"(addr));
        }
        __syncwarp();

#pragma unroll
        for (int nt = 0; nt < 8; nt++) {
            float c0 = 0.f, c1 = 0.f, c2 = 0.f, c3 = 0.f;
#pragma unroll
            for (int kb = 0; kb < 4; kb++) {
                unsigned b0, b1r;
                unsigned addr = w2Base + ((nt * 8 + bRowOfs) * 72 + kb * 16 + bColOfs) * 2;
                asm volatile("ldmatrix.sync.aligned.m8n8.x2.shared.b16 {%0,%1}, [%2];"
                             : "=r"(b0), "=r"(b1r) : "r"(addr));
                asm volatile("mma.sync.aligned.m16n8k16.row.col.f32.f16.f16.f32 "
                             "{%0,%1,%2,%3}, {%4,%5,%6,%7}, {%8,%9}, {%0,%1,%2,%3};"
                             : "+f"(c0), "+f"(c1), "+f"(c2), "+f"(c3)
                             : "r"(A2[kb][0]), "r"(A2[kb][1]), "r"(A2[kb][2]), "r"(A2[kb][3]),
                               "r"(b0), "r"(b1r));
            }
            float bb0 = sb2[nt * 8 + col0], bb1 = sb2[nt * 8 + col0 + 1];
            c0 += bb0; c1 += bb1; c2 += bb0; c3 += bb1;
            *(float2*)&g_t[(size_t)(n0 + r) * NH + nt * 8 + col0] = make_float2(c0, c1);
            *(float2*)&g_t[(size_t)(n0 + r + 8) * NH + nt * 8 + col0] = make_float2(c2, c3);
            st_s[nt * 2 + 0] += c0 + c2;
            st_q[nt * 2 + 0] += c0 * c0 + c2 * c2;
            st_s[nt * 2 + 1] += c1 + c3;
            st_q[nt * 2 + 1] += c1 * c1 + c3 * c3;
        }
        __syncwarp();
    }

#pragma unroll
    for (int i = 0; i < 16; i++) {
#pragma unroll
        for (int o = 4; o < 32; o <<= 1) {
            st_s[i] += __shfl_xor_sync(0xFFFFFFFFu, st_s[i], o);
            st_q[i] += __shfl_xor_sync(0xFFFFFFFFu, st_q[i], o);
        }
    }
    if (lane < 4) {
#pragma unroll
        for (int nt = 0; nt < 8; nt++) {
#pragma unroll
            for (int i = 0; i < 2; i++) {
                int col = nt * 8 + lane * 2 + i;
                atomicAdd(&ssum[col], st_s[nt * 2 + i]);
                atomicAdd(&ssq[col], st_q[nt * 2 + i]);
            }
        }
    }
    __syncthreads();
    if (tid < NH) {
        atomicAdd(&g_stats[l][tid], ssum[tid]);
        atomicAdd(&g_stats[l][NH + tid], ssq[tid]);
    }
}

// ---------------------------------------------------------------------------
// BN apply + ReLU: g_t -> g_h (fp32) + g_hh (fp16 mirror)
// ---------------------------------------------------------------------------
__global__ void bn_kernel(const float* __restrict__ gamma,
                          const float* __restrict__ beta, int l) {
    __shared__ float sc[NH], sh[NH];
    int tid = threadIdx.x;
    if (tid < NH) {
        float m = g_stats[l][tid] * (1.0f / NN);
        float v = g_stats[l][NH + tid] * (1.0f / NN) - m * m;
        float inv = rsqrtf(v + BN_EPS);
        float s = inv * __ldg(gamma + tid);
        sc[tid] = s;
        sh[tid] = __ldg(beta + tid) - m * s;
    }
    __syncthreads();
    for (int i = blockIdx.x * blockDim.x + tid; i < NN * NH / 4;
         i += gridDim.x * blockDim.x) {
        int c4 = (i & (NH / 4 - 1)) * 4;
        float4 v = ((const float4*)g_t)[i];
        v.x = fmaxf(v.x * sc[c4 + 0] + sh[c4 + 0], 0.0f);
        v.y = fmaxf(v.y * sc[c4 + 1] + sh[c4 + 1], 0.0f);
        v.z = fmaxf(v.z * sc[c4 + 2] + sh[c4 + 2], 0.0f);
        v.w = fmaxf(v.w * sc[c4 + 3] + sh[c4 + 3], 0.0f);
        ((float4*)g_h)[i] = v;
        __half2 lo = __floats2half2_rn(v.x, v.y);
        __half2 hi = __floats2half2_rn(v.z, v.w);
        uint2 u;
        u.x = *(unsigned*)&lo;
        u.y = *(unsigned*)&hi;
        *(uint2*)&g_hh[i * 2] = u;
    }
}

// ---------------------------------------------------------------------------
// Fused pool + classifier using SORTED batch: block g binary-searches its
// contiguous node range [lo, hi), applies last-layer BN+ReLU to g_t rows,
// mean-pools, and computes out[g]. No atomics, no intermediate buffers.
// Tail cleanup here: g_deg ONLY (this kernel never reads deg; stats are
// zeroed by hist_kernel at the head of the next launch's side chain).
// ---------------------------------------------------------------------------
__global__ void poolfinal_kernel(const int* __restrict__ batch,
                                 const float* __restrict__ gam_p,
                                 const float* __restrict__ bet_p,
                                 const float* __restrict__ lw,
                                 const float* __restrict__ lb,
                                 float* __restrict__ out) {
    __shared__ float ssc[NH], ssh[NH];
    __shared__ float part[2][NH];
    __shared__ float sp[NH];
    int g = blockIdx.x, tid = threadIdx.x;
    int col = tid & 63, hp = tid >> 6;

    if (tid < NH) {
        float m = g_stats[NL - 1][tid] * (1.0f / NN);
        float v = g_stats[NL - 1][NH + tid] * (1.0f / NN) - m * m;
        float s = rsqrtf(v + BN_EPS) * __ldg(gam_p + tid);
        ssc[tid] = s;
        ssh[tid] = __ldg(bet_p + tid) - m * s;
    }
    __syncthreads();

    // lower_bound(batch, g) and lower_bound(batch, g+1) over sorted batch
    int lo, hi;
    {
        int a = 0, b = NN;
        while (a < b) { int m = (a + b) >> 1; if (__ldg(batch + m) < g) a = m + 1; else b = m; }
        lo = a;
        b = NN;
        while (a < b) { int m = (a + b) >> 1; if (__ldg(batch + m) < g + 1) a = m + 1; else b = m; }
        hi = a;
    }

    float sc = ssc[col], sh = ssh[col];
    float acc = 0.0f;
    for (int n = lo + hp; n < hi; n += 2)
        acc += fmaxf(g_t[(size_t)n * NH + col] * sc + sh, 0.0f);
    part[hp][col] = acc;
    __syncthreads();

    if (tid < NH) {
        float cnt = fmaxf((float)(hi - lo), 1.0f);
        sp[tid] = (part[0][tid] + part[1][tid]) / cnt;
    }
    __syncthreads();

    if (tid < NC) {
        float a = __ldg(lb + tid);
        for (int k = 0; k < NH; k++) a += sp[k] * __ldg(lw + k * NC + tid);
        out[g * NC + tid] = a;
    }

    // ---- tail cleanup: g_deg only (not read by this kernel) ----
    for (int i = g * 128 + tid; i < NN; i += NG * 128) g_deg[i] = 0;
}

// ---------------------------------------------------------------------------
extern "C" void kernel_launch(void* const* d_in, const int* in_sizes, int n_in,
                              void* d_out, int out_size) {
    const float* x     = (const float*)d_in[0];
    const int*   ei    = (const int*)d_in[1];
    const int*   batch = (const int*)d_in[2];
    const float* enc_w = (const float*)d_in[3];
    const float* enc_b = (const float*)d_in[4];
    const float* eps   = (const float*)d_in[5];
    const float* cw1   = (const float*)d_in[6];
    const float* cb1   = (const float*)d_in[7];
    const float* cw2   = (const float*)d_in[8];
    const float* cb2   = (const float*)d_in[9];
    const float* gam   = (const float*)d_in[10];
    const float* bet   = (const float*)d_in[11];
    const float* lw    = (const float*)d_in[12];
    const float* lb    = (const float*)d_in[13];
    float* out = (float*)d_out;

    // One-time host resources (no device memory involved)
    static cudaStream_t s_side = nullptr;
    static cudaEvent_t ev_fork = nullptr, ev_join = nullptr;
    if (s_side == nullptr) {
        cudaStreamCreateWithFlags(&s_side, cudaStreamNonBlocking);
        cudaEventCreateWithFlags(&ev_fork, cudaEventDisableTiming);
        cudaEventCreateWithFlags(&ev_join, cudaEventDisableTiming);
    }

    // Fork: CSR build on side stream, encoder on main stream (independent).
    cudaEventRecord(ev_fork, 0);
    cudaStreamWaitEvent(s_side, ev_fork, 0);

    hist_kernel<<<(NE / 4 + 255) / 256, 256, 0, s_side>>>(ei);
    scan_fused_kernel<<<SCAN_B, 256, 0, s_side>>>();
    fill_kernel<<<(NE / 4 + 255) / 256, 256, 0, s_side>>>(ei);

    enc_kernel<<<EGRID, 256>>>(x, enc_w, enc_b);

    cudaEventRecord(ev_join, s_side);
    cudaStreamWaitEvent(0, ev_join, 0);

    for (int l = 0; l < NL; l++) {
        layer_kernel<<<LGRID, LWARPS * 32>>>(eps + l, l,
                                             cw1 + (size_t)l * NH * NH, cb1 + l * NH,
                                             cw2 + (size_t)l * NH * NH, cb2 + l * NH);
        if (l < NL - 1)
            bn_kernel<<<444, 256>>>(gam + l * NH, bet + l * NH, l);
    }

    poolfinal_kernel<<<NG, 128>>>(batch, gam + 2 * NH, bet + 2 * NH, lw, lb, out);
}